// round 3
// baseline (speedup 1.0000x reference)
#include <cuda_runtime.h>
#include <math.h>

#define NN   1024
#define EIN  4096
#define ET   5120
#define NTE  5119
#define C1   16
#define C2   7
#define INC  1433
#define TE_BLOCK 256
#define NCHUNK  ((NTE + TE_BLOCK - 1) / TE_BLOCK)
#define SORT_M 8192                 // bitonic padded size (pow2 >= NTE)

// ---------------- device scratch ----------------
__device__ float  g_dig[NTE + 1];
__device__ float  g_h1[NN * C1];
__device__ float  g_h2[NN * C2];
__device__ float  g_gx[C1 * NTE], g_gy[C1 * NTE], g_gz[C1 * NTE];
__device__ float  g_sx[C1 * NTE], g_sy[C1 * NTE], g_sz[C1 * NTE];
__device__ unsigned long long g_key[C1 * SORT_M];
__device__ float  g_tesum1[C1];
__device__ float  g_tesum2[C2];
__device__ float  g_agg1[NN * C1];
__device__ float  g_agg2[NN * C2];
__device__ float  g_cnt[NN];

__device__ __forceinline__ float f_inf() { return __int_as_float(0x7f800000); }

// ---------------- zero accumulators ----------------
__global__ void k_zero() {
    int t = blockIdx.x * blockDim.x + threadIdx.x;
    if (t < NN * C1) g_agg1[t] = 0.f;
    if (t < NN * C2) g_agg2[t] = 0.f;
    if (t < NN)      g_cnt[t]  = 0.f;
    if (t < C1)      g_tesum1[t] = 0.f;
    if (t < C2)      g_tesum2[t] = 0.f;
}

// ---------------- digamma table ----------------
__global__ void k_digamma() {
    int k = blockIdx.x * blockDim.x + threadIdx.x;
    if (k > NTE) return;
    if (k == 0) { g_dig[0] = 0.f; return; }
    double x = (double)k, r = 0.0;
    while (x < 8.0) { r -= 1.0 / x; x += 1.0; }
    double ix = 1.0 / x, ix2 = ix * ix;
    r += log(x) - 0.5 * ix
       - ix2 * ((1.0/12.0) - ix2 * ((1.0/120.0) - ix2 * (1.0/252.0)));
    g_dig[k] = (float)r;
}

// ---------------- layer-1 GEMM ----------------
__global__ void k_gemm1(const float* __restrict__ x,
                        const float* __restrict__ W1,
                        const float* __restrict__ b1) {
    int v    = blockIdx.x;
    int warp = threadIdx.x >> 5;
    int lane = threadIdx.x & 31;
    const float* xr = x  + (size_t)v    * INC;
    const float* wr = W1 + (size_t)warp * INC;
    float s = 0.f;
    for (int k = lane; k < INC; k += 32) s += xr[k] * wr[k];
    #pragma unroll
    for (int o = 16; o; o >>= 1) s += __shfl_xor_sync(0xffffffffu, s, o);
    if (lane == 0) g_h1[v * C1 + warp] = s + b1[warp];
}

// ---------------- gather (x,y,z) per channel, SoA ----------------
__global__ void k_gather(const int* __restrict__ ei, int layer, int C) {
    int idx = blockIdx.x * blockDim.x + threadIdx.x;
    if (idx >= C * NTE) return;
    const float* h = (layer == 1) ? g_h1 : g_h2;
    int c = idx / NTE, i = idx - c * NTE;
    int s0 = (i  < EIN) ? ei[i]        : (i - EIN);
    int d0 = (i  < EIN) ? ei[EIN + i]  : (i - EIN);
    int i1 = i + 1;
    int s1 = (i1 < EIN) ? ei[i1]       : (i1 - EIN);
    g_gx[idx] = h[d0 * C + c];
    g_gy[idx] = h[s0 * C + c];
    g_gz[idx] = h[s1 * C + c];
}

// ---------------- per-channel bitonic sort by y (one block / channel) ----------------
__global__ __launch_bounds__(1024) void k_sort() {
    int c = blockIdx.x;
    unsigned long long* key = g_key + (size_t)c * SORT_M;
    const float* gy = g_gy + (size_t)c * NTE;

    for (int t = threadIdx.x; t < SORT_M; t += 1024) {
        if (t < NTE) {
            unsigned u = __float_as_uint(gy[t]);
            u = (u & 0x80000000u) ? ~u : (u | 0x80000000u);   // order-preserving encode
            key[t] = ((unsigned long long)u << 32) | (unsigned)t;
        } else {
            key[t] = 0xFFFFFFFFFFFFFFFFull;
        }
    }
    __syncthreads();

    for (int k = 2; k <= SORT_M; k <<= 1) {
        for (int j = k >> 1; j > 0; j >>= 1) {
            for (int i = threadIdx.x; i < SORT_M; i += 1024) {
                int l = i ^ j;
                if (l > i) {
                    unsigned long long a = key[i], b = key[l];
                    bool up = ((i & k) == 0);
                    if ((a > b) == up) { key[i] = b; key[l] = a; }
                }
            }
            __syncthreads();
        }
    }

    const float* gx = g_gx + (size_t)c * NTE;
    const float* gz = g_gz + (size_t)c * NTE;
    float* sx = g_sx + (size_t)c * NTE;
    float* sy = g_sy + (size_t)c * NTE;
    float* sz = g_sz + (size_t)c * NTE;
    for (int t = threadIdx.x; t < NTE; t += 1024) {
        unsigned idx = (unsigned)(key[t] & 0xFFFFFFFFu);
        sx[t] = gx[idx];
        sy[t] = gy[idx];
        sz[t] = gz[idx];
    }
}

// ---------------- KSG TE via sorted-y window walks ----------------
__global__ __launch_bounds__(TE_BLOCK) void k_te(int layer) {
    float* tesum = (layer == 1) ? g_tesum1 : g_tesum2;
    int c     = blockIdx.x / NCHUNK;
    int chunk = blockIdx.x - c * NCHUNK;
    int p     = chunk * TE_BLOCK + threadIdx.x;

    const float* X = g_sx + (size_t)c * NTE;
    const float* Y = g_sy + (size_t)c * NTE;
    const float* Z = g_sz + (size_t)c * NTE;

    float val = 0.f;
    if (p < NTE) {
        float xi = X[p], yi = Y[p], zi = Z[p];

        // ---- eps: expanding two-pointer search on sorted y ----
        float eps = f_inf();
        int lo = p - 1, hi = p + 1;
        float dyl = (lo >= 0)  ? (yi - Y[lo]) : f_inf();
        float dyr = (hi < NTE) ? (Y[hi] - yi) : f_inf();
        while (true) {
            if (dyl <= dyr) {
                if (dyl >= eps) break;          // min remaining dy >= eps -> done
                float m = fmaxf(dyl, fmaxf(fabsf(xi - X[lo]), fabsf(zi - Z[lo])));
                eps = fminf(eps, m);
                lo--;
                dyl = (lo >= 0) ? (yi - Y[lo]) : f_inf();
            } else {
                if (dyr >= eps) break;
                float m = fmaxf(dyr, fmaxf(fabsf(xi - X[hi]), fabsf(zi - Z[hi])));
                eps = fminf(eps, m);
                hi++;
                dyr = (hi < NTE) ? (Y[hi] - yi) : f_inf();
            }
        }

        // ---- counts over the dy<eps window (self contributes 1 to each) ----
        int cy = 1, cxy = 1, cyz = 1;
        for (int j = p - 1; j >= 0; j--) {
            float dy = yi - Y[j];
            if (!(dy < eps)) break;
            cy++;
            cxy += (fabsf(xi - X[j]) < eps);
            cyz += (fabsf(zi - Z[j]) < eps);
        }
        for (int j = p + 1; j < NTE; j++) {
            float dy = Y[j] - yi;
            if (!(dy < eps)) break;
            cy++;
            cxy += (fabsf(xi - X[j]) < eps);
            cyz += (fabsf(zi - Z[j]) < eps);
        }
        val = g_dig[cy] - g_dig[cxy] - g_dig[cyz];
    }

    #pragma unroll
    for (int o = 16; o; o >>= 1) val += __shfl_xor_sync(0xffffffffu, val, o);
    __shared__ float red[TE_BLOCK / 32];
    int lane = threadIdx.x & 31, w = threadIdx.x >> 5;
    if (lane == 0) red[w] = val;
    __syncthreads();
    if (threadIdx.x == 0) {
        float s = 0.f;
        #pragma unroll
        for (int q = 0; q < TE_BLOCK / 32; q++) s += red[q];
        atomicAdd(&tesum[c], s);
    }
}

// ---------------- aggregation ----------------
__global__ void k_agg(const int* __restrict__ ei, int layer, int C) {
    int idx = blockIdx.x * blockDim.x + threadIdx.x;
    if (idx >= ET * C) return;
    const float* h     = (layer == 1) ? g_h1 : g_h2;
    const float* tesum = (layer == 1) ? g_tesum1 : g_tesum2;
    float*       agg   = (layer == 1) ? g_agg1 : g_agg2;
    int e = idx / C, c = idx - e * C;
    int s = (e < EIN) ? ei[e]       : (e - EIN);
    int d = (e < EIN) ? ei[EIN + e] : (e - EIN);
    float tes = -0.57721566490153286f + tesum[c] * (1.0f / (float)NTE);
    if (layer == 2) tes *= 0.5f;
    float m = 1.0f / (1.0f + expf(-tes * h[s * C + c]));
    atomicAdd(&agg[d * C + c], m);
    if (layer == 1 && c == 0) atomicAdd(&g_cnt[d], 1.0f);
}

// ---------------- layer-2 GEMM ----------------
__global__ void k_gemm2(const float* __restrict__ W2, const float* __restrict__ b2) {
    int v = blockIdx.x * blockDim.x + threadIdx.x;
    if (v >= NN) return;
    float inv = 1.0f / fmaxf(g_cnt[v], 1.0f);
    float hv[C1];
    #pragma unroll
    for (int cc = 0; cc < C1; cc++) hv[cc] = fmaxf(g_agg1[v * C1 + cc] * inv, 0.0f);
    #pragma unroll
    for (int o = 0; o < C2; o++) {
        float s = b2[o];
        #pragma unroll
        for (int cc = 0; cc < C1; cc++) s += W2[o * C1 + cc] * hv[cc];
        g_h2[v * C2 + o] = s;
    }
}

// ---------------- final: mean + log_softmax ----------------
__global__ void k_final(float* __restrict__ out) {
    int v = blockIdx.x * blockDim.x + threadIdx.x;
    if (v >= NN) return;
    float inv = 1.0f / fmaxf(g_cnt[v], 1.0f);
    float val[C2], mx = -f_inf();
    #pragma unroll
    for (int o = 0; o < C2; o++) {
        val[o] = g_agg2[v * C2 + o] * inv;
        mx = fmaxf(mx, val[o]);
    }
    float s = 0.f;
    #pragma unroll
    for (int o = 0; o < C2; o++) s += expf(val[o] - mx);
    float ls = mx + logf(s);
    #pragma unroll
    for (int o = 0; o < C2; o++) out[v * C2 + o] = val[o] - ls;
}

// ---------------- launch (inputs identified by element count) ----------------
extern "C" void kernel_launch(void* const* d_in, const int* in_sizes, int n_in,
                              void* d_out, int out_size) {
    const float* x  = nullptr;
    const int*   ei = nullptr;
    const float* W1 = nullptr;
    const float* b1 = nullptr;
    const float* W2 = nullptr;
    const float* b2 = nullptr;
    for (int k = 0; k < n_in; k++) {
        switch (in_sizes[k]) {
            case NN * INC:  x  = (const float*)d_in[k]; break;
            case 2 * EIN:   ei = (const int*)  d_in[k]; break;
            case C1 * INC:  W1 = (const float*)d_in[k]; break;
            case C1:        b1 = (const float*)d_in[k]; break;
            case C2 * C1:   W2 = (const float*)d_in[k]; break;
            case C2:        b2 = (const float*)d_in[k]; break;
            default: break;
        }
    }
    float* out = (float*)d_out;

    k_zero   <<<(NN * C1 + 255) / 256, 256>>>();
    k_digamma<<<(NTE + 1 + 255) / 256, 256>>>();

    // layer 1
    k_gemm1  <<<NN, 512>>>(x, W1, b1);
    k_gather <<<(C1 * NTE + 255) / 256, 256>>>(ei, 1, C1);
    k_sort   <<<C1, 1024>>>();
    k_te     <<<C1 * NCHUNK, TE_BLOCK>>>(1);
    k_agg    <<<(ET * C1 + 255) / 256, 256>>>(ei, 1, C1);

    // layer 2
    k_gemm2  <<<(NN + 255) / 256, 256>>>(W2, b2);
    k_gather <<<(C2 * NTE + 255) / 256, 256>>>(ei, 2, C2);
    k_sort   <<<C2, 1024>>>();
    k_te     <<<C2 * NCHUNK, TE_BLOCK>>>(2);
    k_agg    <<<(ET * C2 + 255) / 256, 256>>>(ei, 2, C2);

    k_final  <<<(NN + 255) / 256, 256>>>(out);
}